// round 12
// baseline (speedup 1.0000x reference)
#include <cuda_runtime.h>
#include <cuda_bf16.h>
#include <cstdint>
#include <math.h>

#define A_N 1000
#define N_N 2000
#define Z_N 2000
#define D_N 8
#define GK  2048   // padded square dimension for all GEMMs
#define LDA 72     // smem row stride (elems) for GEMM tiles
#define STAGE_BYTES 36864           // (128 A rows + 128 B rows) * 144 B
#define B_OFF 18432                 // B tile offset within a stage
#define NSTAGE 3
#define SMEM_GEMM (NSTAGE * STAGE_BYTES)

// ---------------- device scratch (no cudaMalloc allowed) ----------------
__device__ __nv_bfloat16 g_Kbf [GK * GK];      // K_Z1Z1 bf16 padded
__device__ __nv_bfloat16 g_Bzt [GK * GK];      // K_Z1Z2^T bf16
__device__ __nv_bfloat16 g_gNt [GK * GK];      // gamma_N^T hi
__device__ __nv_bfloat16 g_gNlo[GK * GK];      // gamma_N^T lo
__device__ __nv_bfloat16 g_gMNt[GK * GK];      // gamma_MN^T hi
__device__ __nv_bfloat16 g_gXt [GK * GK];      // gamma_X^T hi
__device__ __nv_bfloat16 g_gXlo[GK * GK];      // gamma_X^T lo
__device__ __nv_bfloat16 g_E1st[GK * GK];      // interleaved E1: row 2a=cos, 2a+1=sin (hi)
__device__ __nv_bfloat16 g_E1lo[GK * GK];
__device__ __nv_bfloat16 g_E2st[GK * GK];
__device__ __nv_bfloat16 g_E2lo[GK * GK];
__device__ __nv_bfloat16 g_W1t [8 * GK * GK];  // all-d weighted gamma, rows (d*2048+z)
__device__ __nv_bfloat16 g_W2t [8 * GK * GK];
__device__ float  g_C1[GK * GK];               // Neumann T1 (C[m][n], ldc 2048)
__device__ float  g_P [GK * GK];               // P = E1 @ gammaN (interleaved rows)
__device__ float  g_U [8 * GK * GK];           // U_all = E1 @ W1 (ldc 16384)
__device__ float4 g_den4[A_N * Z_N];           // [a][z]: {1/|p|^2, 1/|q|^2, rre, rim}
__device__ float  g_acc;

// ---------------- mma / cp.async helpers (portable PTX, valid at compute_103) ----------------
__device__ __forceinline__ uint32_t smem_u32(const void* p) {
  uint32_t a;
  asm("{ .reg .u64 t; cvta.to.shared.u64 t, %1; cvt.u32.u64 %0, t; }" : "=r"(a) : "l"(p));
  return a;
}
__device__ __forceinline__ void ldsm4(uint32_t* r, uint32_t addr) {
  asm volatile("ldmatrix.sync.aligned.m8n8.x4.shared.b16 {%0,%1,%2,%3}, [%4];"
               : "=r"(r[0]), "=r"(r[1]), "=r"(r[2]), "=r"(r[3]) : "r"(addr));
}
__device__ __forceinline__ void mma16816(float* c, const uint32_t* a, const uint32_t* b) {
  asm volatile(
      "mma.sync.aligned.m16n8k16.row.col.f32.bf16.bf16.f32 "
      "{%0,%1,%2,%3}, {%4,%5,%6,%7}, {%8,%9}, {%0,%1,%2,%3};"
      : "+f"(c[0]), "+f"(c[1]), "+f"(c[2]), "+f"(c[3])
      : "r"(a[0]), "r"(a[1]), "r"(a[2]), "r"(a[3]), "r"(b[0]), "r"(b[1]));
}
#define CP_ASYNC16(dst, src) \
  asm volatile("cp.async.cg.shared.global [%0], [%1], 16;" :: "r"(dst), "l"(src))
#define CP_COMMIT() asm volatile("cp.async.commit_group;" ::: "memory")
#define CP_WAIT1()  asm volatile("cp.async.wait_group 1;" ::: "memory")
#define CP_WAIT0()  asm volatile("cp.async.wait_group 0;" ::: "memory")

__device__ __forceinline__ void wr_hilo(__nv_bfloat16* hi, __nv_bfloat16* lo,
                                        size_t o, float v) {
  __nv_bfloat16 h = __float2bfloat16(v);
  hi[o] = h;
  lo[o] = __float2bfloat16(v - __bfloat162float(h));
}

// ---------------- pipelined k-sweep (3-stage cp.async, accumulate into cacc) ----------------
__device__ __forceinline__ void ksweep(
    float (*cacc)[8][4],
    const __nv_bfloat16* A0, const __nv_bfloat16* B0,
    const __nv_bfloat16* A1, const __nv_bfloat16* B1,
    const __nv_bfloat16* A2, const __nv_bfloat16* B2,
    int npairs, int mblk, int nblk,
    uint32_t sdst, uint32_t aAddr, uint32_t bAddr, int srow, int scol) {
  const __nv_bfloat16* Aps[3] = {A0, A1, A2};
  const __nv_bfloat16* Bps[3] = {B0, B1, B2};
  int nch = npairs * 32;

#define KS_ISSUE(CH, SLOT)                                                   \
  do {                                                                       \
    const __nv_bfloat16* _Ap = Aps[(CH) >> 5];                               \
    const __nv_bfloat16* _Bp = Bps[(CH) >> 5];                               \
    int _k0 = ((CH) & 31) * 64;                                              \
    uint32_t _sb = sdst + (SLOT) * STAGE_BYTES;                              \
    _Pragma("unroll")                                                        \
    for (int _p = 0; _p < 4; _p++) {                                         \
      int _row = _p * 32 + srow;                                             \
      CP_ASYNC16(_sb + _p * (32 * LDA * 2),                                  \
                 _Ap + (size_t)(mblk + _row) * GK + _k0 + scol);             \
      CP_ASYNC16(_sb + B_OFF + _p * (32 * LDA * 2),                          \
                 _Bp + (size_t)(nblk + _row) * GK + _k0 + scol);             \
    }                                                                        \
    CP_COMMIT();                                                             \
  } while (0)

  KS_ISSUE(0, 0);
  KS_ISSUE(1, 1);
  int slot = 0, nslot = 2;
  for (int ch = 0; ch < nch; ch++) {
    CP_WAIT1();
    __syncthreads();
    uint32_t soff = (uint32_t)slot * STAGE_BYTES;
#pragma unroll
    for (int ks = 0; ks < 4; ks++) {
      uint32_t af0[4], af1[4];
      ldsm4(af0, aAddr + soff + ks * 32);
      ldsm4(af1, aAddr + soff + 16 * LDA * 2 + ks * 32);
#pragma unroll
      for (int j2 = 0; j2 < 4; j2++) {
        uint32_t bf4[4];
        ldsm4(bf4, bAddr + soff + j2 * (16 * LDA * 2) + ks * 32);
        mma16816(cacc[0][j2 * 2],     af0, bf4);
        mma16816(cacc[0][j2 * 2 + 1], af0, bf4 + 2);
        mma16816(cacc[1][j2 * 2],     af1, bf4);
        mma16816(cacc[1][j2 * 2 + 1], af1, bf4 + 2);
      }
    }
    __syncthreads();
    if (ch + 2 < nch) KS_ISSUE(ch + 2, nslot);
    else CP_COMMIT();
    if (++slot == NSTAGE) slot = 0;
    if (++nslot == NSTAGE) nslot = 0;
  }
  CP_WAIT0();
  __syncthreads();
#undef KS_ISSUE
}

// common per-thread GEMM geometry
#define GEMM_PROLOG                                                              \
  extern __shared__ char sm[];                                                   \
  uint32_t smb = smem_u32(sm);                                                   \
  int tid = threadIdx.x, lane = tid & 31, wid = tid >> 5;                        \
  int wm = wid & 3, wn = wid >> 2;                                               \
  int mblk = blockIdx.y * 128, nblk = blockIdx.x * 128;                          \
  int srow = tid >> 3;                                                           \
  int scol = (tid & 7) * 8;                                                      \
  uint32_t sdst = smb + (uint32_t)((srow * LDA + scol) * 2);                     \
  uint32_t aAddr = smb + (uint32_t)(((wm * 32 + (lane & 15)) * LDA +             \
                                     ((lane >> 4) * 8)) * 2);                    \
  uint32_t bAddr = smb + B_OFF +                                                 \
                   (uint32_t)(((wn * 64 + ((lane >> 4) << 3) + (lane & 7)) * LDA \
                               + (((lane >> 3) & 1) * 8)) * 2);

#define ACC_INIT(c)                                                              \
  float c[2][8][4];                                                              \
  _Pragma("unroll")                                                              \
  for (int _i = 0; _i < 2; _i++)                                                 \
    _Pragma("unroll")                                                            \
    for (int _j = 0; _j < 8; _j++)                                               \
      _Pragma("unroll")                                                          \
      for (int _e = 0; _e < 4; _e++) c[_i][_j][_e] = 0.f;

// ---------------- small kernels ----------------
__global__ void zero_acc_kernel() { g_acc = 0.f; }

// phase features, interleaved complex stacking, hi/lo split
__global__ void trig_kernel(const float* __restrict__ alpha,
                            const float* __restrict__ Nmat,
                            const float* __restrict__ Xmat) {
  int idx = blockIdx.x * blockDim.x + threadIdx.x;   // a*2048 + j
  if (idx >= A_N * GK) return;
  int a = idx >> 11;
  int j = idx & (GK - 1);
  size_t oA = (size_t)(2 * a) * GK + j;       // cos row
  size_t oB = (size_t)(2 * a + 1) * GK + j;   // sin row
  if (j >= N_N) {
    __nv_bfloat16 z = __float2bfloat16(0.f);
    g_E1st[oA] = z; g_E1st[oB] = z; g_E1lo[oA] = z; g_E1lo[oB] = z;
    g_E2st[oA] = z; g_E2st[oB] = z; g_E2lo[oA] = z; g_E2lo[oB] = z;
    return;
  }
  float ph1 = 0.f, ph2 = 0.f;
#pragma unroll
  for (int d = 0; d < D_N; d++) {
    float al = alpha[a * D_N + d];
    ph1 = fmaf(al, Nmat[j * D_N + d], ph1);
    ph2 = fmaf(al, Xmat[j * D_N + d], ph2);
  }
  float s1, c1, s2, c2;
  sincosf(ph1, &s1, &c1);
  sincosf(ph2, &s2, &c2);
  wr_hilo(g_E1st, g_E1lo, oA, c1);
  wr_hilo(g_E1st, g_E1lo, oB, s1);
  wr_hilo(g_E2st, g_E2lo, oA, c2);
  wr_hilo(g_E2st, g_E2lo, oB, s2);
}

// zero pad rows 2000-2047 of the E stacks
__global__ void pad_rows_kernel() {
  int idx = blockIdx.x * blockDim.x + threadIdx.x;   // 48*2048
  if (idx >= 48 * GK) return;
  int row = 2000 + (idx >> 11);
  int col = idx & (GK - 1);
  size_t o = (size_t)row * GK + col;
  __nv_bfloat16 z = __float2bfloat16(0.f);
  g_E1st[o] = z; g_E1lo[o] = z; g_E2st[o] = z; g_E2lo[o] = z;
}

// K_Z1Z1 fp32[2000x2000] -> bf16 [2048x2048] padded
__global__ void cvt_pad_kernel(const float* __restrict__ K) {
  int idx = blockIdx.x * blockDim.x + threadIdx.x;
  if (idx >= GK * GK) return;
  int i = idx >> 11;
  int j = idx & (GK - 1);
  float v = (i < N_N && j < Z_N) ? K[(size_t)i * Z_N + j] : 0.f;
  g_Kbf[idx] = __float2bfloat16(v);
}

// transpose fp32 [2000(n) x 2000(z)] -> bf16 [2048(z) x 2048(n)], optional lo plane
__global__ void transpose_cvt_kernel(const float* __restrict__ in,
                                     __nv_bfloat16* __restrict__ outHi,
                                     __nv_bfloat16* __restrict__ outLo,
                                     int withLo) {
  __shared__ float t[32][33];
  int n0 = blockIdx.x * 32, z0 = blockIdx.y * 32;
  int tx = threadIdx.x, ty = threadIdx.y;
#pragma unroll
  for (int dy = 0; dy < 4; dy++) {
    int n = n0 + ty + dy * 8, z = z0 + tx;
    t[ty + dy * 8][tx] = (n < N_N && z < Z_N) ? in[(size_t)n * Z_N + z] : 0.f;
  }
  __syncthreads();
#pragma unroll
  for (int dy = 0; dy < 4; dy++) {
    int z = z0 + ty + dy * 8, n = n0 + tx;
    float v = t[tx][ty + dy * 8];
    size_t o = (size_t)z * GK + n;
    __nv_bfloat16 h = __float2bfloat16(v);
    outHi[o] = h;
    if (withLo) outLo[o] = __float2bfloat16(v - __bfloat162float(h));
  }
}

// ---------------- generic GEMM with store (single accumulator; proven in R8) ----------------
__global__ __launch_bounds__(256) void gemm_cp(
    const __nv_bfloat16* __restrict__ A0, const __nv_bfloat16* __restrict__ B0,
    const __nv_bfloat16* __restrict__ A1, const __nv_bfloat16* __restrict__ B1,
    const __nv_bfloat16* __restrict__ A2, const __nv_bfloat16* __restrict__ B2,
    int npairs, float* __restrict__ C, int ldc) {
  GEMM_PROLOG
  ACC_INIT(c)
  ksweep(c, A0, B0, A1, B1, A2, B2, npairs, mblk, nblk, sdst, aAddr, bAddr, srow, scol);
  int r0 = mblk + wm * 32 + (lane >> 2);
  int c0 = nblk + wn * 64 + (lane & 3) * 2;
#pragma unroll
  for (int i = 0; i < 2; i++)
#pragma unroll
    for (int j = 0; j < 8; j++) {
      int row = r0 + i * 16;
      int col = c0 + j * 8;
      *reinterpret_cast<float2*>(&C[(size_t)row * ldc + col]) =
          make_float2(c[i][j][0], c[i][j][1]);
      *reinterpret_cast<float2*>(&C[(size_t)(row + 8) * ldc + col]) =
          make_float2(c[i][j][2], c[i][j][3]);
    }
}

// ---------------- Q GEMM (split-bf16) + den4 epilogue reading P ----------------
__global__ __launch_bounds__(256) void gemm_den_q(
    const __nv_bfloat16* __restrict__ E2, const __nv_bfloat16* __restrict__ E2lo,
    const __nv_bfloat16* __restrict__ gX, const __nv_bfloat16* __restrict__ gXlo) {
  GEMM_PROLOG
  ACC_INIT(cQ)
  ksweep(cQ, E2, gX, E2, gXlo, E2lo, gX, 3, mblk, nblk, sdst, aAddr, bAddr, srow, scol);

  bool even = ((lane >> 2) & 1) == 0;
  int rbase = mblk + wm * 32 + (lane >> 2);
  int cbase = nblk + wn * 64 + (lane & 3) * 2;
#pragma unroll
  for (int i = 0; i < 2; i++)
#pragma unroll
    for (int j = 0; j < 8; j++) {
      float qO[4], qP[4];
#pragma unroll
      for (int e = 0; e < 4; e++) {
        qO[e] = cQ[i][j][e];
        qP[e] = __shfl_xor_sync(0xffffffffu, qO[e], 4);
      }
      if (even) {
#pragma unroll
        for (int h = 0; h < 2; h++) {
          int row = rbase + i * 16 + h * 8;     // even row = 2a
          int a = row >> 1;
          if (a >= A_N) continue;
#pragma unroll
          for (int e2 = 0; e2 < 2; e2++) {
            int e = h * 2 + e2;
            int z = cbase + j * 8 + e2;
            if (z >= Z_N) continue;
            float pr = g_P[(size_t)row * GK + z];
            float pi = g_P[(size_t)(row + 1) * GK + z];
            float qr = qO[e], qi = qP[e];
            float ipp = 1.f / fmaf(pr, pr, pi * pi);
            float iqq = 1.f / fmaf(qr, qr, qi * qi);
            float sre = fmaf(pr, qr, pi * qi);
            float sim = fmaf(pi, qr, -pr * qi);
            float f = ipp * iqq;
            g_den4[(size_t)a * Z_N + z] = make_float4(ipp, iqq, sre * f, -sim * f);
          }
        }
      }
    }
}

// ---------------- V GEMM + loss epilogue reading U_all and den4 ----------------
__global__ __launch_bounds__(256) void gemm_loss_v(
    const __nv_bfloat16* __restrict__ E2, const __nv_bfloat16* __restrict__ W2) {
  GEMM_PROLOG
  __shared__ float red[256];
  ACC_INIT(cV)
  ksweep(cV, E2, W2, E2, W2, E2, W2, 1, mblk, nblk, sdst, aAddr, bAddr, srow, scol);

  const size_t LDU = 8 * GK;
  bool even = ((lane >> 2) & 1) == 0;
  int rbase = mblk + wm * 32 + (lane >> 2);
  int cbase = nblk + wn * 64 + (lane & 3) * 2;
  float lsum = 0.f;
#pragma unroll
  for (int i = 0; i < 2; i++)
#pragma unroll
    for (int j = 0; j < 8; j++) {
      float vO[4], vP[4];
#pragma unroll
      for (int e = 0; e < 4; e++) {
        vO[e] = cV[i][j][e];
        vP[e] = __shfl_xor_sync(0xffffffffu, vO[e], 4);
      }
      if (even) {
#pragma unroll
        for (int h = 0; h < 2; h++) {
          int row = rbase + i * 16 + h * 8;     // even row = 2a
          int a = row >> 1;
          if (a >= A_N) continue;
#pragma unroll
          for (int e2 = 0; e2 < 2; e2++) {
            int e = h * 2 + e2;
            int colg = cbase + j * 8 + e2;      // d*2048 + z
            int z = colg & (GK - 1);
            if (z >= Z_N) continue;
            float ur = g_U[(size_t)row * LDU + colg];
            float ui = g_U[(size_t)(row + 1) * LDU + colg];
            float vr = vO[e], vi = vP[e];
            float4 dn = g_den4[(size_t)a * Z_N + z];
            float uu = fmaf(ur, ur, ui * ui);
            float vv = fmaf(vr, vr, vi * vi);
            float xr = fmaf(ur, vr, ui * vi);
            float xi = fmaf(ui, vr, -ur * vi);
            lsum += fmaf(uu, dn.x, vv * dn.y) - 2.f * fmaf(xr, dn.z, -xi * dn.w);
          }
        }
      }
    }
  red[tid] = lsum;
  __syncthreads();
  for (int s = 128; s > 0; s >>= 1) {
    if (tid < s) red[tid] += red[tid + s];
    __syncthreads();
  }
  if (tid == 0) atomicAdd(&g_acc, red[0]);
}

// gamma_X^T: reads Bz[k][z] fp32 and T1=g_C1[k][z] (ldc 2048), writes gXt[z][k] hi+lo
__global__ void combine_t_kernel(const float* __restrict__ B,
                                 const float* __restrict__ loglam) {
  __shared__ float t[32][33];
  float ic = 1.f / ((float)N_N * expf(loglam[0]));
  int k0 = blockIdx.x * 32, z0 = blockIdx.y * 32;
  int tx = threadIdx.x, ty = threadIdx.y;
#pragma unroll
  for (int dy = 0; dy < 4; dy++) {
    int k = k0 + ty + dy * 8, z = z0 + tx;
    float v = 0.f;
    if (k < N_N && z < Z_N)
      v = (B[(size_t)k * Z_N + z] - g_C1[(size_t)k * GK + z] * ic) * ic;
    t[ty + dy * 8][tx] = v;
  }
  __syncthreads();
#pragma unroll
  for (int dy = 0; dy < 4; dy++) {
    int z = z0 + ty + dy * 8, k = k0 + tx;
    size_t o = (size_t)z * GK + k;
    wr_hilo(g_gXt, g_gXlo, o, t[tx][ty + dy * 8]);
  }
}

// W[(d*2048+z)][k] = bf16(Gt[z][k] * MX[k][d]) for all 8 d in one pass
__global__ void prepW_all_kernel(const __nv_bfloat16* __restrict__ Gt,
                                 const float* __restrict__ MX,
                                 __nv_bfloat16* __restrict__ W) {
  int idx8 = blockIdx.x * blockDim.x + threadIdx.x;  // 2048 * 256
  if (idx8 >= GK * (GK / 8)) return;
  int z = idx8 >> 8;
  int k8 = (idx8 & 255) << 3;
  uint4 gv = *reinterpret_cast<const uint4*>(Gt + (size_t)z * GK + k8);
  const __nv_bfloat16* gp = reinterpret_cast<const __nv_bfloat16*>(&gv);
  float gf[8];
#pragma unroll
  for (int e = 0; e < 8; e++) gf[e] = __bfloat162float(gp[e]);
#pragma unroll
  for (int d = 0; d < D_N; d++) {
    uint4 ov;
    __nv_bfloat16* op = reinterpret_cast<__nv_bfloat16*>(&ov);
#pragma unroll
    for (int e = 0; e < 8; e++) {
      int k = k8 + e;
      float md = (k < N_N) ? MX[k * D_N + d] : 0.f;
      op[e] = __float2bfloat16(gf[e] * md);
    }
    *reinterpret_cast<uint4*>(W + (size_t)(d * GK + z) * GK + k8) = ov;
  }
}

__global__ void finalize_kernel(float* out) {
  out[0] = g_acc * (1.f / (float)(A_N * Z_N));
}

// ---------------- launch ----------------
extern "C" void kernel_launch(void* const* d_in, const int* in_sizes, int n_in,
                              void* d_out, int out_size) {
  const float* Mmat  = (const float*)d_in[0];
  const float* Nmat  = (const float*)d_in[1];
  const float* Xmat  = (const float*)d_in[2];
  const float* llam  = (const float*)d_in[3];
  const float* Kz    = (const float*)d_in[4];
  const float* Bz    = (const float*)d_in[5];
  const float* gMN   = (const float*)d_in[6];
  const float* gN    = (const float*)d_in[7];
  const float* alpha = (const float*)d_in[8];
  float* out = (float*)d_out;

  cudaFuncSetAttribute(gemm_cp,     cudaFuncAttributeMaxDynamicSharedMemorySize, SMEM_GEMM);
  cudaFuncSetAttribute(gemm_den_q,  cudaFuncAttributeMaxDynamicSharedMemorySize, SMEM_GEMM);
  cudaFuncSetAttribute(gemm_loss_v, cudaFuncAttributeMaxDynamicSharedMemorySize, SMEM_GEMM);

  __nv_bfloat16 *pKbf, *pBzt, *pgNt, *pgNlo, *pgMNt, *pgXt, *pgXlo;
  __nv_bfloat16 *pE1, *pE1lo, *pE2, *pE2lo, *pW1, *pW2;
  float *pC1, *pP, *pU;
  cudaGetSymbolAddress((void**)&pKbf,  g_Kbf);
  cudaGetSymbolAddress((void**)&pBzt,  g_Bzt);
  cudaGetSymbolAddress((void**)&pgNt,  g_gNt);
  cudaGetSymbolAddress((void**)&pgNlo, g_gNlo);
  cudaGetSymbolAddress((void**)&pgMNt, g_gMNt);
  cudaGetSymbolAddress((void**)&pgXt,  g_gXt);
  cudaGetSymbolAddress((void**)&pgXlo, g_gXlo);
  cudaGetSymbolAddress((void**)&pE1,   g_E1st);
  cudaGetSymbolAddress((void**)&pE1lo, g_E1lo);
  cudaGetSymbolAddress((void**)&pE2,   g_E2st);
  cudaGetSymbolAddress((void**)&pE2lo, g_E2lo);
  cudaGetSymbolAddress((void**)&pW1,   g_W1t);
  cudaGetSymbolAddress((void**)&pW2,   g_W2t);
  cudaGetSymbolAddress((void**)&pC1,   g_C1);
  cudaGetSymbolAddress((void**)&pP,    g_P);
  cudaGetSymbolAddress((void**)&pU,    g_U);

  dim3 t32(32, 8);
  dim3 g64(64, 64);
  dim3 gg(16, 16);          // square GEMMs
  dim3 ggl(128, 16);        // batched numerator GEMMs

  zero_acc_kernel<<<1, 1>>>();
  trig_kernel<<<(A_N * GK) / 256, 256>>>(alpha, Nmat, Xmat);
  pad_rows_kernel<<<(48 * GK) / 256, 256>>>();
  cvt_pad_kernel<<<(GK * GK) / 256, 256>>>(Kz);
  transpose_cvt_kernel<<<g64, t32>>>(Bz, pBzt, pBzt, 0);
  transpose_cvt_kernel<<<g64, t32>>>(gN, pgNt, pgNlo, 1);
  transpose_cvt_kernel<<<g64, t32>>>(gMN, pgMNt, pgMNt, 0);

  // Neumann (1 term): T1[i][z] = (K @ B)[i][z]
  gemm_cp<<<gg, 256, SMEM_GEMM>>>(pKbf, pBzt, pKbf, pBzt, pKbf, pBzt, 1, pC1, GK);
  combine_t_kernel<<<g64, t32>>>(Bz, llam);

  // weighted gammas for all 8 d
  prepW_all_kernel<<<(GK * GK / 8) / 256, 256>>>(pgMNt, Mmat, pW1);
  prepW_all_kernel<<<(GK * GK / 8) / 256, 256>>>(pgXt, Xmat, pW2);

  // denominators: P materialized (16MB), Q fused with den4 epilogue
  gemm_cp<<<gg, 256, SMEM_GEMM>>>(pE1, pgNt, pE1, pgNlo, pE1lo, pgNt, 3, pP, GK);
  gemm_den_q<<<gg, 256, SMEM_GEMM>>>(pE2, pE2lo, pgXt, pgXlo);

  // numerators: U_all materialized (128MB), V fused with loss epilogue
  gemm_cp<<<ggl, 256, SMEM_GEMM>>>(pE1, pW1, pE1, pW1, pE1, pW1, 1, pU, 8 * GK);
  gemm_loss_v<<<ggl, 256, SMEM_GEMM>>>(pE2, pW2);

  finalize_kernel<<<1, 1>>>(out);
}

// round 15
// speedup vs baseline: 1.7524x; 1.7524x over previous
#include <cuda_runtime.h>
#include <cuda_bf16.h>
#include <cstdint>
#include <math.h>

#define A_N 1000
#define N_N 2000
#define Z_N 2000
#define D_N 8
#define GK  2048   // padded square dimension for all GEMMs
#define LDA 72     // smem row stride (elems) for GEMM tiles
#define STAGE_BYTES 36864           // (128 A rows + 128 B rows) * 144 B
#define B_OFF 18432                 // B tile offset within a stage
#define NSTAGE 3
#define SMEM_GEMM (NSTAGE * STAGE_BYTES)
#define LDC_S 132                   // padded smem C-tile row stride (floats)

// ---------------- device scratch (no cudaMalloc allowed) ----------------
__device__ __nv_bfloat16 g_Kbf [GK * GK];      // K_Z1Z1 bf16 padded
__device__ __nv_bfloat16 g_Bzt [GK * GK];      // K_Z1Z2^T bf16
__device__ __nv_bfloat16 g_gNt [GK * GK];      // gamma_N^T hi
__device__ __nv_bfloat16 g_gNlo[GK * GK];      // gamma_N^T lo
__device__ __nv_bfloat16 g_gMNt[GK * GK];      // gamma_MN^T hi
__device__ __nv_bfloat16 g_gXt [GK * GK];      // gamma_X^T hi
__device__ __nv_bfloat16 g_gXlo[GK * GK];      // gamma_X^T lo
__device__ __nv_bfloat16 g_E1st[GK * GK];      // interleaved E1: row 2a=cos, 2a+1=sin (hi)
__device__ __nv_bfloat16 g_E1lo[GK * GK];
__device__ __nv_bfloat16 g_E2st[GK * GK];
__device__ __nv_bfloat16 g_E2lo[GK * GK];
__device__ __nv_bfloat16 g_W1t [8 * GK * GK];  // all-d weighted gamma, rows (d*2048+z)
__device__ __nv_bfloat16 g_W2t [8 * GK * GK];
__device__ float  g_C1[GK * GK];               // Neumann T1 (C[m][n], ldc 2048)
__device__ float  g_P [GK * GK];               // P = E1 @ gammaN (interleaved rows)
__device__ float  g_Q [GK * GK];               // Q = E2 @ gammaX (interleaved rows)
__device__ float  g_U [8 * GK * GK];           // U_all = E1 @ W1 (ldc 16384)
__device__ float4 g_den4[A_N * Z_N];           // [a][z]: {1/|p|^2, 1/|q|^2, rre, rim}
__device__ float  g_acc;

// ---------------- mma / cp.async helpers (portable PTX, valid at compute_103) ----------------
__device__ __forceinline__ uint32_t smem_u32(const void* p) {
  uint32_t a;
  asm("{ .reg .u64 t; cvta.to.shared.u64 t, %1; cvt.u32.u64 %0, t; }" : "=r"(a) : "l"(p));
  return a;
}
__device__ __forceinline__ void ldsm4(uint32_t* r, uint32_t addr) {
  asm volatile("ldmatrix.sync.aligned.m8n8.x4.shared.b16 {%0,%1,%2,%3}, [%4];"
               : "=r"(r[0]), "=r"(r[1]), "=r"(r[2]), "=r"(r[3]) : "r"(addr));
}
__device__ __forceinline__ void mma16816(float* c, const uint32_t* a, const uint32_t* b) {
  asm volatile(
      "mma.sync.aligned.m16n8k16.row.col.f32.bf16.bf16.f32 "
      "{%0,%1,%2,%3}, {%4,%5,%6,%7}, {%8,%9}, {%0,%1,%2,%3};"
      : "+f"(c[0]), "+f"(c[1]), "+f"(c[2]), "+f"(c[3])
      : "r"(a[0]), "r"(a[1]), "r"(a[2]), "r"(a[3]), "r"(b[0]), "r"(b[1]));
}
#define CP_ASYNC16(dst, src) \
  asm volatile("cp.async.cg.shared.global [%0], [%1], 16;" :: "r"(dst), "l"(src))
#define CP_COMMIT() asm volatile("cp.async.commit_group;" ::: "memory")
#define CP_WAIT1()  asm volatile("cp.async.wait_group 1;" ::: "memory")
#define CP_WAIT0()  asm volatile("cp.async.wait_group 0;" ::: "memory")

__device__ __forceinline__ void wr_hilo(__nv_bfloat16* hi, __nv_bfloat16* lo,
                                        size_t o, float v) {
  __nv_bfloat16 h = __float2bfloat16(v);
  hi[o] = h;
  lo[o] = __float2bfloat16(v - __bfloat162float(h));
}

// ---------------- pipelined k-sweep (3-stage cp.async, single barrier per chunk) ----------------
__device__ __forceinline__ void ksweep(
    float (*cacc)[8][4],
    const __nv_bfloat16* A0, const __nv_bfloat16* B0,
    const __nv_bfloat16* A1, const __nv_bfloat16* B1,
    const __nv_bfloat16* A2, const __nv_bfloat16* B2,
    int npairs, int mblk, int nblk,
    uint32_t sdst, uint32_t aAddr, uint32_t bAddr, int srow, int scol) {
  const __nv_bfloat16* Aps[3] = {A0, A1, A2};
  const __nv_bfloat16* Bps[3] = {B0, B1, B2};
  int nch = npairs * 32;

#define KS_ISSUE(CH, SLOT)                                                   \
  do {                                                                       \
    const __nv_bfloat16* _Ap = Aps[(CH) >> 5];                               \
    const __nv_bfloat16* _Bp = Bps[(CH) >> 5];                               \
    int _k0 = ((CH) & 31) * 64;                                              \
    uint32_t _sb = sdst + (SLOT) * STAGE_BYTES;                              \
    _Pragma("unroll")                                                        \
    for (int _p = 0; _p < 4; _p++) {                                         \
      int _row = _p * 32 + srow;                                             \
      CP_ASYNC16(_sb + _p * (32 * LDA * 2),                                  \
                 _Ap + (size_t)(mblk + _row) * GK + _k0 + scol);             \
      CP_ASYNC16(_sb + B_OFF + _p * (32 * LDA * 2),                          \
                 _Bp + (size_t)(nblk + _row) * GK + _k0 + scol);             \
    }                                                                        \
    CP_COMMIT();                                                             \
  } while (0)

  KS_ISSUE(0, 0);
  KS_ISSUE(1, 1);
  int slot = 0, nslot = 2;
  for (int ch = 0; ch < nch; ch++) {
    CP_WAIT1();
    __syncthreads();
    uint32_t soff = (uint32_t)slot * STAGE_BYTES;
#pragma unroll
    for (int ks = 0; ks < 4; ks++) {
      uint32_t af0[4], af1[4];
      ldsm4(af0, aAddr + soff + ks * 32);
      ldsm4(af1, aAddr + soff + 16 * LDA * 2 + ks * 32);
#pragma unroll
      for (int j2 = 0; j2 < 4; j2++) {
        uint32_t bf4[4];
        ldsm4(bf4, bAddr + soff + j2 * (16 * LDA * 2) + ks * 32);
        mma16816(cacc[0][j2 * 2],     af0, bf4);
        mma16816(cacc[0][j2 * 2 + 1], af0, bf4 + 2);
        mma16816(cacc[1][j2 * 2],     af1, bf4);
        mma16816(cacc[1][j2 * 2 + 1], af1, bf4 + 2);
      }
    }
    // NOTE: no second barrier. The next-iteration barrier guarantees all warps
    // finished compute of ch-1 (slot (ch-1)%3 == (ch+2)%3) before that slot is
    // overwritten — cp.async below targets a slot no warp can still be reading.
    if (ch + 2 < nch) KS_ISSUE(ch + 2, nslot);
    else CP_COMMIT();
    if (++slot == NSTAGE) slot = 0;
    if (++nslot == NSTAGE) nslot = 0;
  }
  CP_WAIT0();
  __syncthreads();
#undef KS_ISSUE
}

// common per-thread GEMM geometry
#define GEMM_PROLOG                                                              \
  extern __shared__ char sm[];                                                   \
  uint32_t smb = smem_u32(sm);                                                   \
  int tid = threadIdx.x, lane = tid & 31, wid = tid >> 5;                        \
  int wm = wid & 3, wn = wid >> 2;                                               \
  int mblk = blockIdx.y * 128, nblk = blockIdx.x * 128;                          \
  int srow = tid >> 3;                                                           \
  int scol = (tid & 7) * 8;                                                      \
  uint32_t sdst = smb + (uint32_t)((srow * LDA + scol) * 2);                     \
  uint32_t aAddr = smb + (uint32_t)(((wm * 32 + (lane & 15)) * LDA +             \
                                     ((lane >> 4) * 8)) * 2);                    \
  uint32_t bAddr = smb + B_OFF +                                                 \
                   (uint32_t)(((wn * 64 + ((lane >> 4) << 3) + (lane & 7)) * LDA \
                               + (((lane >> 3) & 1) * 8)) * 2);

#define ACC_INIT(c)                                                              \
  float c[2][8][4];                                                              \
  _Pragma("unroll")                                                              \
  for (int _i = 0; _i < 2; _i++)                                                 \
    _Pragma("unroll")                                                            \
    for (int _j = 0; _j < 8; _j++)                                               \
      _Pragma("unroll")                                                          \
      for (int _e = 0; _e < 4; _e++) c[_i][_j][_e] = 0.f;

// ---------------- small kernels ----------------
__global__ void zero_acc_kernel() { g_acc = 0.f; }

// phase features, interleaved complex stacking, hi/lo split
__global__ void trig_kernel(const float* __restrict__ alpha,
                            const float* __restrict__ Nmat,
                            const float* __restrict__ Xmat) {
  int idx = blockIdx.x * blockDim.x + threadIdx.x;   // a*2048 + j
  if (idx >= A_N * GK) return;
  int a = idx >> 11;
  int j = idx & (GK - 1);
  size_t oA = (size_t)(2 * a) * GK + j;       // cos row
  size_t oB = (size_t)(2 * a + 1) * GK + j;   // sin row
  if (j >= N_N) {
    __nv_bfloat16 z = __float2bfloat16(0.f);
    g_E1st[oA] = z; g_E1st[oB] = z; g_E1lo[oA] = z; g_E1lo[oB] = z;
    g_E2st[oA] = z; g_E2st[oB] = z; g_E2lo[oA] = z; g_E2lo[oB] = z;
    return;
  }
  float ph1 = 0.f, ph2 = 0.f;
#pragma unroll
  for (int d = 0; d < D_N; d++) {
    float al = alpha[a * D_N + d];
    ph1 = fmaf(al, Nmat[j * D_N + d], ph1);
    ph2 = fmaf(al, Xmat[j * D_N + d], ph2);
  }
  float s1, c1, s2, c2;
  sincosf(ph1, &s1, &c1);
  sincosf(ph2, &s2, &c2);
  wr_hilo(g_E1st, g_E1lo, oA, c1);
  wr_hilo(g_E1st, g_E1lo, oB, s1);
  wr_hilo(g_E2st, g_E2lo, oA, c2);
  wr_hilo(g_E2st, g_E2lo, oB, s2);
}

// zero pad rows 2000-2047 of the E stacks
__global__ void pad_rows_kernel() {
  int idx = blockIdx.x * blockDim.x + threadIdx.x;   // 48*2048
  if (idx >= 48 * GK) return;
  int row = 2000 + (idx >> 11);
  int col = idx & (GK - 1);
  size_t o = (size_t)row * GK + col;
  __nv_bfloat16 z = __float2bfloat16(0.f);
  g_E1st[o] = z; g_E1lo[o] = z; g_E2st[o] = z; g_E2lo[o] = z;
}

// K_Z1Z1 fp32[2000x2000] -> bf16 [2048x2048] padded
__global__ void cvt_pad_kernel(const float* __restrict__ K) {
  int idx = blockIdx.x * blockDim.x + threadIdx.x;
  if (idx >= GK * GK) return;
  int i = idx >> 11;
  int j = idx & (GK - 1);
  float v = (i < N_N && j < Z_N) ? K[(size_t)i * Z_N + j] : 0.f;
  g_Kbf[idx] = __float2bfloat16(v);
}

// transpose fp32 [2000(n) x 2000(z)] -> bf16 [2048(z) x 2048(n)], optional lo plane
__global__ void transpose_cvt_kernel(const float* __restrict__ in,
                                     __nv_bfloat16* __restrict__ outHi,
                                     __nv_bfloat16* __restrict__ outLo,
                                     int withLo) {
  __shared__ float t[32][33];
  int n0 = blockIdx.x * 32, z0 = blockIdx.y * 32;
  int tx = threadIdx.x, ty = threadIdx.y;
#pragma unroll
  for (int dy = 0; dy < 4; dy++) {
    int n = n0 + ty + dy * 8, z = z0 + tx;
    t[ty + dy * 8][tx] = (n < N_N && z < Z_N) ? in[(size_t)n * Z_N + z] : 0.f;
  }
  __syncthreads();
#pragma unroll
  for (int dy = 0; dy < 4; dy++) {
    int z = z0 + ty + dy * 8, n = n0 + tx;
    float v = t[tx][ty + dy * 8];
    size_t o = (size_t)z * GK + n;
    __nv_bfloat16 h = __float2bfloat16(v);
    outHi[o] = h;
    if (withLo) outLo[o] = __float2bfloat16(v - __bfloat162float(h));
  }
}

// ---------------- generic GEMM with store (single accumulator; proven) ----------------
__global__ __launch_bounds__(256) void gemm_cp(
    const __nv_bfloat16* __restrict__ A0, const __nv_bfloat16* __restrict__ B0,
    const __nv_bfloat16* __restrict__ A1, const __nv_bfloat16* __restrict__ B1,
    const __nv_bfloat16* __restrict__ A2, const __nv_bfloat16* __restrict__ B2,
    int npairs, float* __restrict__ C, int ldc) {
  GEMM_PROLOG
  ACC_INIT(c)
  ksweep(c, A0, B0, A1, B1, A2, B2, npairs, mblk, nblk, sdst, aAddr, bAddr, srow, scol);
  int r0 = mblk + wm * 32 + (lane >> 2);
  int c0 = nblk + wn * 64 + (lane & 3) * 2;
#pragma unroll
  for (int i = 0; i < 2; i++)
#pragma unroll
    for (int j = 0; j < 8; j++) {
      int row = r0 + i * 16;
      int col = c0 + j * 8;
      *reinterpret_cast<float2*>(&C[(size_t)row * ldc + col]) =
          make_float2(c[i][j][0], c[i][j][1]);
      *reinterpret_cast<float2*>(&C[(size_t)(row + 8) * ldc + col]) =
          make_float2(c[i][j][2], c[i][j][3]);
    }
}

// ---------------- V GEMM + smem-staged coalesced loss epilogue ----------------
__global__ __launch_bounds__(256) void gemm_loss_v(
    const __nv_bfloat16* __restrict__ E2, const __nv_bfloat16* __restrict__ W2) {
  GEMM_PROLOG
  __shared__ float red[256];
  ACC_INIT(cV)
  ksweep(cV, E2, W2, E2, W2, E2, W2, 1, mblk, nblk, sdst, aAddr, bAddr, srow, scol);

  // stage C tile to smem (padded rows to avoid bank conflicts)
  float* Cs = reinterpret_cast<float*>(sm);
  int r0 = wm * 32 + (lane >> 2);
  int c0 = wn * 64 + (lane & 3) * 2;
#pragma unroll
  for (int i = 0; i < 2; i++)
#pragma unroll
    for (int j = 0; j < 8; j++) {
      int row = r0 + i * 16;
      int col = c0 + j * 8;
      Cs[row * LDC_S + col]           = cV[i][j][0];
      Cs[row * LDC_S + col + 1]       = cV[i][j][1];
      Cs[(row + 8) * LDC_S + col]     = cV[i][j][2];
      Cs[(row + 8) * LDC_S + col + 1] = cV[i][j][3];
    }
  __syncthreads();

  // cooperative coalesced loss pass: warp=even-row, lanes=consecutive cols
  const size_t LDU = 8 * GK;
  float lsum = 0.f;
#pragma unroll
  for (int it = 0; it < 8; it++) {
    int er = it * 8 + wid;            // even-row index within tile: 0..63
    int grow = mblk + 2 * er;         // global even row (= 2a)
    int a = grow >> 1;
    if (a < A_N) {
#pragma unroll
      for (int cc = 0; cc < 4; cc++) {
        int col = cc * 32 + lane;
        int colg = nblk + col;         // d*2048 + z
        int z = colg & (GK - 1);
        if (z < Z_N) {
          float vr = Cs[(2 * er) * LDC_S + col];
          float vi = Cs[(2 * er + 1) * LDC_S + col];
          float ur = g_U[(size_t)grow * LDU + colg];
          float ui = g_U[(size_t)(grow + 1) * LDU + colg];
          float4 dn = g_den4[(size_t)a * Z_N + z];
          float uu = fmaf(ur, ur, ui * ui);
          float vv = fmaf(vr, vr, vi * vi);
          float xr = fmaf(ur, vr, ui * vi);
          float xi = fmaf(ui, vr, -ur * vi);
          lsum += fmaf(uu, dn.x, vv * dn.y) - 2.f * fmaf(xr, dn.z, -xi * dn.w);
        }
      }
    }
  }
  red[tid] = lsum;
  __syncthreads();
  for (int s = 128; s > 0; s >>= 1) {
    if (tid < s) red[tid] += red[tid + s];
    __syncthreads();
  }
  if (tid == 0) atomicAdd(&g_acc, red[0]);
}

// gamma_X^T: reads Bz[k][z] fp32 and T1=g_C1[k][z] (ldc 2048), writes gXt[z][k] hi+lo
__global__ void combine_t_kernel(const float* __restrict__ B,
                                 const float* __restrict__ loglam) {
  __shared__ float t[32][33];
  float ic = 1.f / ((float)N_N * expf(loglam[0]));
  int k0 = blockIdx.x * 32, z0 = blockIdx.y * 32;
  int tx = threadIdx.x, ty = threadIdx.y;
#pragma unroll
  for (int dy = 0; dy < 4; dy++) {
    int k = k0 + ty + dy * 8, z = z0 + tx;
    float v = 0.f;
    if (k < N_N && z < Z_N)
      v = (B[(size_t)k * Z_N + z] - g_C1[(size_t)k * GK + z] * ic) * ic;
    t[ty + dy * 8][tx] = v;
  }
  __syncthreads();
#pragma unroll
  for (int dy = 0; dy < 4; dy++) {
    int z = z0 + ty + dy * 8, k = k0 + tx;
    size_t o = (size_t)z * GK + k;
    wr_hilo(g_gXt, g_gXlo, o, t[tx][ty + dy * 8]);
  }
}

// W[(d*2048+z)][k] = bf16(Gt[z][k] * MX[k][d]) for all 8 d in one pass
__global__ void prepW_all_kernel(const __nv_bfloat16* __restrict__ Gt,
                                 const float* __restrict__ MX,
                                 __nv_bfloat16* __restrict__ W) {
  int idx8 = blockIdx.x * blockDim.x + threadIdx.x;  // 2048 * 256
  if (idx8 >= GK * (GK / 8)) return;
  int z = idx8 >> 8;
  int k8 = (idx8 & 255) << 3;
  uint4 gv = *reinterpret_cast<const uint4*>(Gt + (size_t)z * GK + k8);
  const __nv_bfloat16* gp = reinterpret_cast<const __nv_bfloat16*>(&gv);
  float gf[8];
#pragma unroll
  for (int e = 0; e < 8; e++) gf[e] = __bfloat162float(gp[e]);
#pragma unroll
  for (int d = 0; d < D_N; d++) {
    uint4 ov;
    __nv_bfloat16* op = reinterpret_cast<__nv_bfloat16*>(&ov);
#pragma unroll
    for (int e = 0; e < 8; e++) {
      int k = k8 + e;
      float md = (k < N_N) ? MX[k * D_N + d] : 0.f;
      op[e] = __float2bfloat16(gf[e] * md);
    }
    *reinterpret_cast<uint4*>(W + (size_t)(d * GK + z) * GK + k8) = ov;
  }
}

// denominator planes from interleaved P, Q; grid (8, A_N)
__global__ void den4_kernel() {
  int z = blockIdx.x * blockDim.x + threadIdx.x;
  int a = blockIdx.y;
  if (z >= Z_N) return;
  float pr = g_P[(size_t)(2 * a) * GK + z], pi = g_P[(size_t)(2 * a + 1) * GK + z];
  float qr = g_Q[(size_t)(2 * a) * GK + z], qi = g_Q[(size_t)(2 * a + 1) * GK + z];
  float ipp = 1.f / fmaf(pr, pr, pi * pi);
  float iqq = 1.f / fmaf(qr, qr, qi * qi);
  float sre = fmaf(pr, qr, pi * qi);
  float sim = fmaf(pi, qr, -pr * qi);
  float f = ipp * iqq;
  g_den4[(size_t)a * Z_N + z] = make_float4(ipp, iqq, sre * f, -sim * f);
}

__global__ void finalize_kernel(float* out) {
  out[0] = g_acc * (1.f / (float)(A_N * Z_N));
}

// ---------------- launch ----------------
extern "C" void kernel_launch(void* const* d_in, const int* in_sizes, int n_in,
                              void* d_out, int out_size) {
  const float* Mmat  = (const float*)d_in[0];
  const float* Nmat  = (const float*)d_in[1];
  const float* Xmat  = (const float*)d_in[2];
  const float* llam  = (const float*)d_in[3];
  const float* Kz    = (const float*)d_in[4];
  const float* Bz    = (const float*)d_in[5];
  const float* gMN   = (const float*)d_in[6];
  const float* gN    = (const float*)d_in[7];
  const float* alpha = (const float*)d_in[8];
  float* out = (float*)d_out;

  cudaFuncSetAttribute(gemm_cp,     cudaFuncAttributeMaxDynamicSharedMemorySize, SMEM_GEMM);
  cudaFuncSetAttribute(gemm_loss_v, cudaFuncAttributeMaxDynamicSharedMemorySize, SMEM_GEMM);

  __nv_bfloat16 *pKbf, *pBzt, *pgNt, *pgNlo, *pgMNt, *pgXt, *pgXlo;
  __nv_bfloat16 *pE1, *pE1lo, *pE2, *pE2lo, *pW1, *pW2;
  float *pC1, *pP, *pQ, *pU;
  cudaGetSymbolAddress((void**)&pKbf,  g_Kbf);
  cudaGetSymbolAddress((void**)&pBzt,  g_Bzt);
  cudaGetSymbolAddress((void**)&pgNt,  g_gNt);
  cudaGetSymbolAddress((void**)&pgNlo, g_gNlo);
  cudaGetSymbolAddress((void**)&pgMNt, g_gMNt);
  cudaGetSymbolAddress((void**)&pgXt,  g_gXt);
  cudaGetSymbolAddress((void**)&pgXlo, g_gXlo);
  cudaGetSymbolAddress((void**)&pE1,   g_E1st);
  cudaGetSymbolAddress((void**)&pE1lo, g_E1lo);
  cudaGetSymbolAddress((void**)&pE2,   g_E2st);
  cudaGetSymbolAddress((void**)&pE2lo, g_E2lo);
  cudaGetSymbolAddress((void**)&pW1,   g_W1t);
  cudaGetSymbolAddress((void**)&pW2,   g_W2t);
  cudaGetSymbolAddress((void**)&pC1,   g_C1);
  cudaGetSymbolAddress((void**)&pP,    g_P);
  cudaGetSymbolAddress((void**)&pQ,    g_Q);
  cudaGetSymbolAddress((void**)&pU,    g_U);

  dim3 t32(32, 8);
  dim3 g64(64, 64);
  dim3 gg(16, 16);          // square GEMMs
  dim3 ggl(128, 16);        // batched numerator GEMMs
  dim3 gel(8, A_N);

  zero_acc_kernel<<<1, 1>>>();
  trig_kernel<<<(A_N * GK) / 256, 256>>>(alpha, Nmat, Xmat);
  pad_rows_kernel<<<(48 * GK) / 256, 256>>>();
  cvt_pad_kernel<<<(GK * GK) / 256, 256>>>(Kz);
  transpose_cvt_kernel<<<g64, t32>>>(Bz, pBzt, pBzt, 0);
  transpose_cvt_kernel<<<g64, t32>>>(gN, pgNt, pgNlo, 1);
  transpose_cvt_kernel<<<g64, t32>>>(gMN, pgMNt, pgMNt, 0);

  // Neumann (1 term): T1[i][z] = (K @ B)[i][z]
  gemm_cp<<<gg, 256, SMEM_GEMM>>>(pKbf, pBzt, pKbf, pBzt, pKbf, pBzt, 1, pC1, GK);
  combine_t_kernel<<<g64, t32>>>(Bz, llam);

  // weighted gammas for all 8 d
  prepW_all_kernel<<<(GK * GK / 8) / 256, 256>>>(pgMNt, Mmat, pW1);
  prepW_all_kernel<<<(GK * GK / 8) / 256, 256>>>(pgXt, Xmat, pW2);

  // denominators (split-bf16, both sides materialized; small 16MB tensors)
  gemm_cp<<<gg, 256, SMEM_GEMM>>>(pE1, pgNt, pE1, pgNlo, pE1lo, pgNt, 3, pP, GK);
  gemm_cp<<<gg, 256, SMEM_GEMM>>>(pE2, pgXt, pE2, pgXlo, pE2lo, pgXt, 3, pQ, GK);
  den4_kernel<<<gel, 256>>>();

  // numerators: U_all materialized; V fused with smem-staged coalesced loss epilogue
  gemm_cp<<<ggl, 256, SMEM_GEMM>>>(pE1, pW1, pE1, pW1, pE1, pW1, 1, pU, 8 * GK);
  gemm_loss_v<<<ggl, 256, SMEM_GEMM>>>(pE2, pW2);

  finalize_kernel<<<1, 1>>>(out);
}